// round 2
// baseline (speedup 1.0000x reference)
#include <cuda_runtime.h>
#include <math.h>

#define BB   32
#define SS   512
#define INF  512
#define HH   1024
#define NG   4096
#define NCTA 128

// Scratch (static device globals — allocation-free per harness rules)
__device__ float g_gxT[(size_t)SS * NG * BB];   // x-part gates, [s][n][b]
__device__ float g_out0[(size_t)BB * SS * HH];  // layer0 outputs [b][s][h]
__device__ float g_hG[2][HH * BB];              // ping-pong h, layout [k4][b][4]
__device__ unsigned g_barCnt;
__device__ unsigned g_barRel;

// ---------------------------------------------------------------------------
__global__ void init_kernel() {
    int idx = blockIdx.x * blockDim.x + threadIdx.x;
    if (idx < HH * BB) g_hG[0][idx] = 0.0f;
    if (idx == 0) { g_barCnt = 0u; g_barRel = 0u; }
}

// ---------------------------------------------------------------------------
// gxT[s][n][b] = sum_k A[m][k] * W[n][k] + bias[n],  m = b*SS + s
__global__ __launch_bounds__(256) void gemm_xpart(
    const float* __restrict__ Ain, int lda,
    const float* __restrict__ W,   int ldw,
    const float* __restrict__ bias, int K, int use_out0)
{
    const float* A = use_out0 ? g_out0 : Ain;

    __shared__ float As[16][68];
    __shared__ float Bs[16][68];

    const int tid  = threadIdx.x;
    const int tx   = tid & 15;
    const int ty   = tid >> 4;
    const int row0 = blockIdx.y * 64;
    const int col0 = blockIdx.x * 64;

    const int li = tid >> 2;
    const int lk = (tid & 3) * 4;

    float acc[4][4];
#pragma unroll
    for (int i = 0; i < 4; i++)
#pragma unroll
        for (int j = 0; j < 4; j++) acc[i][j] = 0.0f;

    for (int k0 = 0; k0 < K; k0 += 16) {
        float4 av = *(const float4*)(A + (size_t)(row0 + li) * lda + k0 + lk);
        float4 bv = *(const float4*)(W + (size_t)(col0 + li) * ldw + k0 + lk);
        As[lk + 0][li] = av.x; As[lk + 1][li] = av.y;
        As[lk + 2][li] = av.z; As[lk + 3][li] = av.w;
        Bs[lk + 0][li] = bv.x; Bs[lk + 1][li] = bv.y;
        Bs[lk + 2][li] = bv.z; Bs[lk + 3][li] = bv.w;
        __syncthreads();

#pragma unroll
        for (int kk = 0; kk < 16; kk++) {
            float4 a4 = *(const float4*)&As[kk][ty * 4];
            float4 b4 = *(const float4*)&Bs[kk][tx * 4];
            float ar[4] = {a4.x, a4.y, a4.z, a4.w};
            float br[4] = {b4.x, b4.y, b4.z, b4.w};
#pragma unroll
            for (int i = 0; i < 4; i++)
#pragma unroll
                for (int j = 0; j < 4; j++) acc[i][j] += ar[i] * br[j];
        }
        __syncthreads();
    }

#pragma unroll
    for (int ii = 0; ii < 4; ii++) {
        int m = row0 + ty * 4 + ii;
        int b = m >> 9;
        int s = m & 511;
#pragma unroll
        for (int jj = 0; jj < 4; jj++) {
            int n = col0 + tx * 4 + jj;
            g_gxT[((size_t)s * NG + n) * BB + b] = acc[ii][jj] + bias[n];
        }
    }
}

// ---------------------------------------------------------------------------
// Persistent recurrent kernel: one launch runs all SS timesteps of one layer.
// 128 CTAs x 256 threads, 1 CTA/SM guaranteed by smem (=> software grid
// barrier is safe). CTA owns 8 hidden units (32 gate rows); its Wh slice
// (128 KB fp32) lives in smem for the whole kernel.
//
// Smem: Wsm 32768 floats (layout [k4][l][4]) + hc 8192 floats (staged h chunk,
// [g][k4i][b][4]) + part 8*32*33 floats (k-split partials) = 197,632 B.
#define SMEM_FLOATS (32768 + 8192 + 8448)

__global__ __launch_bounds__(256, 1) void lstm_layer(
    const float* __restrict__ W, int ldw, int Din,
    float* __restrict__ out, int layer)
{
    extern __shared__ float sm[];
    float* Wsm  = sm;               // 32768 floats
    float* hc   = sm + 32768;       // 8192 floats
    float* part = sm + 32768 + 8192;// 8448 floats

    const int tid = threadIdx.x;
    const int cta = blockIdx.x;
    const int j0  = cta * 8;

    // --- Load Wh slice once: Wsm[(k4*32 + l)*4 + *] = W[n(l)][Din + k4*4 + *]
    for (int i = 0; i < 32; i++) {
        int q  = i * 256 + tid;          // [0, 8192)
        int l  = q & 31;
        int k4 = q >> 5;
        int gate = l >> 3, jj = l & 7;
        int n = gate * 1024 + j0 + jj;
        *(float4*)&Wsm[q * 4] =
            *(const float4*)(W + (size_t)n * ldw + Din + k4 * 4);
    }

    // compute role: k-group g (0..7, 128 k each), micro-tile 4b x 8n
    const int g  = tid >> 5;
    const int gt = tid & 31;
    const int b0 = (gt & 7) * 4;
    const int l0 = (gt >> 3) * 8;
    // update role: (jj, b)
    const int ub = tid & 31;
    const int uj = tid >> 5;
    const int ujglob = j0 + uj;

    float c_state = 0.0f;
    float h_last  = 0.0f;
    unsigned round = 0;

    __syncthreads();

    for (int t = 0; t < SS; t++) {
        // ---- grid barrier (sense via monotonic round counter) ----
        round++;
        __syncthreads();
        if (tid == 0) {
            __threadfence();
            unsigned arrived = atomicAdd(&g_barCnt, 1u) + 1u;
            if (arrived == round * NCTA) {
                atomicExch(&g_barRel, round);
            } else {
                while (atomicAdd(&g_barRel, 0u) < round) { __nanosleep(128); }
            }
            __threadfence();
        }
        __syncthreads();

        const float* hin = g_hG[t & 1];

        float acc[4][8];
#pragma unroll
        for (int bb = 0; bb < 4; bb++)
#pragma unroll
            for (int nn = 0; nn < 8; nn++) acc[bb][nn] = 0.0f;

        for (int cch = 0; cch < 4; cch++) {
            // stage h chunk (32 KB): q -> (gg, k4i, b)
#pragma unroll
            for (int i = 0; i < 8; i++) {
                int q   = i * 256 + tid;       // [0, 2048)
                int b   = q & 31;
                int idx = q >> 5;              // 0..63
                int gg  = idx >> 3, k4i = idx & 7;
                int k4  = gg * 32 + cch * 8 + k4i;
                *(float4*)&hc[q * 4] =
                    __ldcg((const float4*)&hin[(k4 * 32 + b) * 4]);
            }
            __syncthreads();
#pragma unroll
            for (int k4i = 0; k4i < 8; k4i++) {
                int k4    = g * 32 + cch * 8 + k4i;
                int hbase = (g * 8 + k4i) * 32;
                float4 hv[4];
#pragma unroll
                for (int bb = 0; bb < 4; bb++)
                    hv[bb] = *(float4*)&hc[(hbase + b0 + bb) * 4];
#pragma unroll
                for (int nn = 0; nn < 8; nn++) {
                    float4 wv = *(float4*)&Wsm[(k4 * 32 + l0 + nn) * 4];
#pragma unroll
                    for (int bb = 0; bb < 4; bb++)
                        acc[bb][nn] += hv[bb].x * wv.x + hv[bb].y * wv.y
                                     + hv[bb].z * wv.z + hv[bb].w * wv.w;
                }
            }
            __syncthreads();
        }

        // ---- k-split partials -> smem
#pragma unroll
        for (int nn = 0; nn < 8; nn++)
#pragma unroll
            for (int bb = 0; bb < 4; bb++)
                part[(g * 32 + l0 + nn) * 33 + b0 + bb] = acc[bb][nn];
        __syncthreads();

        // ---- reduce + activations + state update (thread = (uj, ub))
        {
            size_t gbase = ((size_t)t * NG + ujglob) * BB + ub;
            float pi = g_gxT[gbase];
            float pf = g_gxT[gbase + (size_t)1024 * BB];
            float pg = g_gxT[gbase + (size_t)2048 * BB];
            float po = g_gxT[gbase + (size_t)3072 * BB];
#pragma unroll
            for (int gg = 0; gg < 8; gg++) {
                pi += part[(gg * 32 +  0 + uj) * 33 + ub];
                pf += part[(gg * 32 +  8 + uj) * 33 + ub];
                pg += part[(gg * 32 + 16 + uj) * 33 + ub];
                po += part[(gg * 32 + 24 + uj) * 33 + ub];
            }
            float gi = 1.0f / (1.0f + expf(-pi));
            float gf = 1.0f / (1.0f + expf(-pf));
            float gg_ = tanhf(pg);
            float go = 1.0f / (1.0f + expf(-po));
            c_state = gf * c_state + gi * gg_;
            float h = go * tanhf(c_state);
            h_last = h;
            __stcg(&g_hG[(t + 1) & 1][((ujglob >> 2) * 32 + ub) * 4 + (ujglob & 3)], h);
            if (layer == 0)
                g_out0[((size_t)ub * SS + t) * HH + ujglob] = h;
        }
        // no extra sync: next iteration's barrier+syncthreads protects hc/part
    }

    // ---- finals
    out[32768 + layer * 32768 + ub * 1024 + ujglob] = h_last;   // h_n
    out[98304 + layer * 32768 + ub * 1024 + ujglob] = c_state;  // c_n
    if (layer == 1) out[ub * 1024 + ujglob] = h_last;           // out1[:, -1, :]
}

// ---------------------------------------------------------------------------
extern "C" void kernel_launch(void* const* d_in, const int* in_sizes, int n_in,
                              void* d_out, int out_size)
{
    const float* x  = (const float*)d_in[0];
    const float* W0 = (const float*)d_in[1];
    const float* b0 = (const float*)d_in[2];
    const float* W1 = (const float*)d_in[3];
    const float* b1 = (const float*)d_in[4];
    float* out = (float*)d_out;

    static int configured = 0;
    if (!configured) {
        cudaFuncSetAttribute(lstm_layer,
            cudaFuncAttributeMaxDynamicSharedMemorySize, SMEM_FLOATS * 4);
        configured = 1;
    }
    const int smem = SMEM_FLOATS * 4;

    // ---- Layer 0 ----
    init_kernel<<<128, 256>>>();
    gemm_xpart<<<dim3(64, 256), 256>>>(x, INF, W0, INF + HH, b0, INF, 0);
    lstm_layer<<<NCTA, 256, smem>>>(W0, INF + HH, INF, out, 0);

    // ---- Layer 1 ----
    init_kernel<<<128, 256>>>();
    gemm_xpart<<<dim3(64, 256), 256>>>(nullptr, HH, W1, HH + HH, b1, HH, 1);
    lstm_layer<<<NCTA, 256, smem>>>(W1, HH + HH, HH, out, 1);
}